// round 13
// baseline (speedup 1.0000x reference)
#include <cuda_runtime.h>

#define N_ATOMS 6144
#define FEAT    128
#define KE_KCAL 332.0637
#define TB 96                          // tile side / block threads
#define GI (N_ATOMS / TB)              // 64
#define NTRI (GI * (GI + 1) / 2)       // 2080 triangular tiles
#define NW (TB / 32)                   // 3 warps per block

__device__ float  g_pred[N_ATOMS];
__device__ float  g_q[N_ATOMS];
__device__ float4 g_p[N_ATOMS];        // x, y, z, sq
__device__ double g_bsum[384];         // per-block pred sums (k_charge)
__device__ double g_part[NTRI];        // per-tile energy partials
__device__ int    g_count = 0;         // last-block-out counter (self-resetting)

// Single-instruction MUFU.RSQ.
__device__ __forceinline__ float rsq(float x) {
    float y;
    asm("rsqrt.approx.f32 %0, %1;" : "=f"(y) : "f"(x));
    return y;
}

// ---------------------------------------------------------------------------
// Kernel 1: pred[i] = f[i].w + z_table[z[i]]  (2 atoms per warp for MLP)
// ---------------------------------------------------------------------------
__global__ __launch_bounds__(256) void k_charge(
    const float4* __restrict__ f4, const int* __restrict__ z,
    const float4* __restrict__ w4, const float* __restrict__ ztab)
{
    __shared__ double bsum[8];
    int tid   = threadIdx.x;
    int gwarp = (blockIdx.x * 256 + tid) >> 5;
    int lane  = tid & 31;
    int a0 = gwarp * 2, a1 = a0 + 1;
    float4 va = f4[(size_t)a0 * (FEAT / 4) + lane];
    float4 vb = f4[(size_t)a1 * (FEAT / 4) + lane];
    float4 wv = w4[lane];
    float s0 = fmaf(va.w, wv.w, fmaf(va.z, wv.z, fmaf(va.y, wv.y, va.x * wv.x)));
    float s1 = fmaf(vb.w, wv.w, fmaf(vb.z, wv.z, fmaf(vb.y, wv.y, vb.x * wv.x)));
#pragma unroll
    for (int o = 16; o; o >>= 1) {
        s0 += __shfl_xor_sync(0xffffffffu, s0, o);
        s1 += __shfl_xor_sync(0xffffffffu, s1, o);
    }
    if (lane == 0) {
        float p0 = s0 + ztab[z[a0]];
        float p1 = s1 + ztab[z[a1]];
        g_pred[a0] = p0;
        g_pred[a1] = p1;
        bsum[tid >> 5] = (double)p0 + (double)p1;
    }
    __syncthreads();
    if (tid == 0) {
        double t = 0.0;
#pragma unroll
        for (int k = 0; k < 8; k++) t += bsum[k];
        g_bsum[blockIdx.x] = t;
    }
}

// ---------------------------------------------------------------------------
// Kernel 2: every block re-reduces g_bsum identically (deterministic),
//           computes correction, then q + packed {x,y,z,sq}.
// ---------------------------------------------------------------------------
__global__ __launch_bounds__(256) void k_q(
    const float* __restrict__ xyz, const float* __restrict__ tc,
    float* __restrict__ q_out)
{
    __shared__ double ws[8];
    __shared__ float  s_corr;
    int tid = threadIdx.x;

    double s = g_bsum[tid] + ((tid < 128) ? g_bsum[tid + 256] : 0.0);
#pragma unroll
    for (int o = 16; o; o >>= 1)
        s += __shfl_xor_sync(0xffffffffu, s, o);
    if ((tid & 31) == 0) ws[tid >> 5] = s;
    __syncthreads();
    if (tid == 0) {
        double tot = 0.0;
#pragma unroll
        for (int k = 0; k < 8; k++) tot += ws[k];
        s_corr = (float)(((double)tc[0] - tot) / (double)N_ATOMS);
    }
    __syncthreads();

    int i = blockIdx.x * 256 + tid;
    float q = g_pred[i] + s_corr;
    g_q[i] = q;
    q_out[i] = q;
    float x = xyz[3 * i + 0], y = xyz[3 * i + 1], zc = xyz[3 * i + 2];
    // EXACT fma ordering reused in k_pairs so the i==j diagonal cancels to 0.
    float sq = fmaf(zc, zc, fmaf(y, y, x * x));
    g_p[i] = make_float4(x, y, zc, sq);
}

// ---------------------------------------------------------------------------
// Dummy kernel: aligns the ncu capture (4th launch) onto k_pairs.
// ---------------------------------------------------------------------------
__global__ void k_dummy() {}

// ---------------------------------------------------------------------------
// Kernel 3: pairwise energy, 96x96 triangular tiles (2080 blocks -> ~14
// blocks/SM resident, 42 warps/SM). Inner loop identical to R12:
// branch-free, single-MUFU rsq, per-thread bitmask fixup for r2 < 56.25.
// Off-diagonal tiles weighted 2x (term i<->j symmetric).
// ---------------------------------------------------------------------------
__global__ __launch_bounds__(TB) void k_pairs(float* __restrict__ out)
{
    __shared__ float4 sp[TB];
    __shared__ float  sqv[TB];
    __shared__ double wsum[NW];
    __shared__ int    s_last;

    int tid = threadIdx.x;

    // linear tile id -> (bx, by), bx <= by
    int rem = blockIdx.x, by = 0;
    while (rem > by) { rem -= by + 1; by++; }
    int bx = rem;

    int i  = bx * TB + tid;
    int j0 = by * TB;

    sp[tid]  = g_p[j0 + tid];
    sqv[tid] = g_q[j0 + tid];
    __syncthreads();

    float4 pi = g_p[i];
    float  qi = g_q[i];
    float  acc = 0.f;

#pragma unroll
    for (int w = 0; w < TB / 32; w++) {
        unsigned m = 0;
#pragma unroll
        for (int b = 0; b < 32; b++) {
            int j = w * 32 + b;
            float4 pj = sp[j];
            float dot = fmaf(pi.z, pj.z, fmaf(pi.y, pj.y, pi.x * pj.x));
            float r2  = fmaf(-2.f, dot, pi.w + pj.w);
            float r2e = fmaxf(r2, 1e-6f);        // diagonal/negative -> finite
            if (r2e < 56.25f) m |= (1u << b);    // predicated OR, no branch
            acc = fmaf(sqv[j], rsq(r2e), acc);   // q_j / r for every pair
        }
        // Fixup: lanes walk their own (rare) bits concurrently.
        while (m) {
            int b = __ffs(m) - 1;
            m &= m - 1;
            int j = w * 32 + b;
            float4 pj = sp[j];
            float dot = fmaf(pi.z, pj.z, fmaf(pi.y, pj.y, pi.x * pj.x));
            float r2  = fmaf(-2.f, dot, pi.w + pj.w);
            float r2e = fmaxf(r2, 1e-6f);
            acc = fmaf(-sqv[j], rsq(r2e), acc);  // remove bogus term (bitwise)
            if (r2 > 0.f) {                       // reference mask
                float term;
                if (r2 <= 6.25f) {
                    term = rsq(r2 + 1.f);         // fs == 1
                } else {
                    float ir  = rsq(r2);
                    float r   = r2 * ir;          // r = sqrt(r2), 1-MUFU form
                    float arg = (r - 2.5f) * 0.2f;  // in (0,1)
                    float su  = __expf(-__fdividef(1.f, 1.f - arg));
                    float sd  = __expf(-__fdividef(1.f, arg));
                    float fs  = __fdividef(su, su + sd);
                    term = fmaf(fs, rsq(r2 + 1.f), (1.f - fs) * ir);
                }
                acc = fmaf(sqv[j], term, acc);
            }
        }
    }
    double a = (double)(acc * qi);
    if (bx != by) a *= 2.0;

    int lane = tid & 31, wid = tid >> 5;
#pragma unroll
    for (int o = 16; o; o >>= 1)
        a += __shfl_xor_sync(0xffffffffu, a, o);
    if (lane == 0) wsum[wid] = a;
    __syncthreads();
    if (tid == 0) {
        double t = 0.0;
#pragma unroll
        for (int k = 0; k < NW; k++) t += wsum[k];
        g_part[blockIdx.x] = t;
        __threadfence();
        int old = atomicAdd(&g_count, 1);
        s_last = (old == NTRI - 1);
    }
    __syncthreads();

    if (s_last) {                          // last block: final reduction
        __threadfence();
        double s = 0.0;
        for (int k = tid; k < NTRI; k += TB)   // fixed order -> deterministic
            s += g_part[k];
#pragma unroll
        for (int o = 16; o; o >>= 1)
            s += __shfl_xor_sync(0xffffffffu, s, o);
        if (lane == 0) wsum[wid] = s;
        __syncthreads();
        if (tid == 0) {
            double tot = 0.0;
#pragma unroll
            for (int k = 0; k < NW; k++) tot += wsum[k];
            out[0] = (float)(KE_KCAL * 0.5 * tot);
            g_count = 0;                   // reset for next graph replay
        }
    }
}

// ---------------------------------------------------------------------------
extern "C" void kernel_launch(void* const* d_in, const int* in_sizes, int n_in,
                              void* d_out, int out_size)
{
    const float* f    = (const float*)d_in[0];
    const int*   z    = (const int*)  d_in[1];
    const float* xyz  = (const float*)d_in[2];
    const float* tc   = (const float*)d_in[3];
    const float* w    = (const float*)d_in[4];
    const float* ztab = (const float*)d_in[5];
    float* out = (float*)d_out;

    k_charge<<<384, 256>>>((const float4*)f, z, (const float4*)w, ztab);
    k_q<<<N_ATOMS / 256, 256>>>(xyz, tc, out + 1);
    k_dummy<<<1, 32>>>();                  // profiling alignment (capture = launch #4)
    k_pairs<<<NTRI, TB>>>(out);
}

// round 14
// speedup vs baseline: 1.1414x; 1.1414x over previous
#include <cuda_runtime.h>

#define N_ATOMS 6144
#define FEAT    128
#define KE_KCAL 332.0637
#define MT 256                         // macro-tile side
#define GM (N_ATOMS / MT)              // 24
#define NTRI (GM * (GM + 1) / 2)       // 300 macro-tiles
#define NBLK (4 * NTRI)                // 1200 blocks (j-quarters)
#define JS 64                          // j's per block
#define TB 128                         // threads per block (2 i-atoms each)

__device__ float  g_pred[N_ATOMS];
__device__ float  g_q[N_ATOMS];
__device__ float4 g_p[N_ATOMS];        // x, y, z, sq
__device__ double g_bsum[384];         // per-block pred sums (k_charge)
__device__ double g_part[NBLK];        // per-block energy partials
__device__ int    g_count = 0;         // last-block-out counter (self-resetting)

// Single-instruction MUFU.RSQ.
__device__ __forceinline__ float rsq(float x) {
    float y;
    asm("rsqrt.approx.f32 %0, %1;" : "=f"(y) : "f"(x));
    return y;
}

// ---------------------------------------------------------------------------
// Kernel 1: pred[i] = f[i].w + z_table[z[i]]  (2 atoms per warp for MLP)
// ---------------------------------------------------------------------------
__global__ __launch_bounds__(256) void k_charge(
    const float4* __restrict__ f4, const int* __restrict__ z,
    const float4* __restrict__ w4, const float* __restrict__ ztab)
{
    __shared__ double bsum[8];
    int tid   = threadIdx.x;
    int gwarp = (blockIdx.x * 256 + tid) >> 5;
    int lane  = tid & 31;
    int a0 = gwarp * 2, a1 = a0 + 1;
    float4 va = f4[(size_t)a0 * (FEAT / 4) + lane];
    float4 vb = f4[(size_t)a1 * (FEAT / 4) + lane];
    float4 wv = w4[lane];
    float s0 = fmaf(va.w, wv.w, fmaf(va.z, wv.z, fmaf(va.y, wv.y, va.x * wv.x)));
    float s1 = fmaf(vb.w, wv.w, fmaf(vb.z, wv.z, fmaf(vb.y, wv.y, vb.x * wv.x)));
#pragma unroll
    for (int o = 16; o; o >>= 1) {
        s0 += __shfl_xor_sync(0xffffffffu, s0, o);
        s1 += __shfl_xor_sync(0xffffffffu, s1, o);
    }
    if (lane == 0) {
        float p0 = s0 + ztab[z[a0]];
        float p1 = s1 + ztab[z[a1]];
        g_pred[a0] = p0;
        g_pred[a1] = p1;
        bsum[tid >> 5] = (double)p0 + (double)p1;
    }
    __syncthreads();
    if (tid == 0) {
        double t = 0.0;
#pragma unroll
        for (int k = 0; k < 8; k++) t += bsum[k];
        g_bsum[blockIdx.x] = t;
    }
}

// ---------------------------------------------------------------------------
// Kernel 2: every block re-reduces g_bsum identically (deterministic),
//           computes correction, then q + packed {x,y,z,sq}.
// ---------------------------------------------------------------------------
__global__ __launch_bounds__(256) void k_q(
    const float* __restrict__ xyz, const float* __restrict__ tc,
    float* __restrict__ q_out)
{
    __shared__ double ws[8];
    __shared__ float  s_corr;
    int tid = threadIdx.x;

    double s = g_bsum[tid] + ((tid < 128) ? g_bsum[tid + 256] : 0.0);
#pragma unroll
    for (int o = 16; o; o >>= 1)
        s += __shfl_xor_sync(0xffffffffu, s, o);
    if ((tid & 31) == 0) ws[tid >> 5] = s;
    __syncthreads();
    if (tid == 0) {
        double tot = 0.0;
#pragma unroll
        for (int k = 0; k < 8; k++) tot += ws[k];
        s_corr = (float)(((double)tc[0] - tot) / (double)N_ATOMS);
    }
    __syncthreads();

    int i = blockIdx.x * 256 + tid;
    float q = g_pred[i] + s_corr;
    g_q[i] = q;
    q_out[i] = q;
    float x = xyz[3 * i + 0], y = xyz[3 * i + 1], zc = xyz[3 * i + 2];
    // EXACT fma ordering reused in k_pairs so the i==j diagonal cancels to 0.
    float sq = fmaf(zc, zc, fmaf(y, y, x * x));
    g_p[i] = make_float4(x, y, zc, sq);
}

// ---------------------------------------------------------------------------
// Dummy kernel: aligns the ncu capture (4th launch) onto k_pairs.
// ---------------------------------------------------------------------------
__global__ void k_dummy() {}

// ---------------------------------------------------------------------------
// Kernel 3: pairwise energy. 256x256 triangular macro-tiles (300), each split
// into 4 j-quarter blocks (1200 blocks x 128 threads). Each thread owns TWO
// i-atoms (i, i+128): per-j shared loads + classify are amortized over 2
// pairs, and the two chains give ILP=2. Branch-free main loop, per-thread
// bitmask fixup for r2 < 56.25. Off-diagonal macro-tiles weighted 2x.
// ---------------------------------------------------------------------------
__global__ __launch_bounds__(TB) void k_pairs(float* __restrict__ out)
{
    __shared__ float4 sp[JS];
    __shared__ float  sqv[JS];
    __shared__ double wsum[TB / 32];
    __shared__ int    s_last;

    int tid = threadIdx.x;

    int tile = blockIdx.x >> 2;
    int quar = blockIdx.x & 3;

    // linear macro-tile id -> (bx, by), bx <= by  (24x24 triangle)
    int rem = tile, by = 0;
    while (rem > by) { rem -= by + 1; by++; }
    int bx = rem;

    int i0 = bx * MT + tid;            // first i-atom
    int i1 = i0 + TB;                  // second i-atom
    int j0 = by * MT + quar * JS;

    if (tid < JS) {
        sp[tid]  = g_p[j0 + tid];
        sqv[tid] = g_q[j0 + tid];
    }
    __syncthreads();

    float4 pa = g_p[i0];
    float4 pb = g_p[i1];
    float  qa = g_q[i0];
    float  qb = g_q[i1];
    float  acc0 = 0.f, acc1 = 0.f;

#pragma unroll
    for (int w = 0; w < JS / 32; w++) {
        unsigned m0 = 0, m1 = 0;
#pragma unroll
        for (int b = 0; b < 32; b++) {
            int j = w * 32 + b;
            float4 pj = sp[j];
            float qj  = sqv[j];
            float dot0 = fmaf(pa.z, pj.z, fmaf(pa.y, pj.y, pa.x * pj.x));
            float dot1 = fmaf(pb.z, pj.z, fmaf(pb.y, pj.y, pb.x * pj.x));
            float r20  = fmaf(-2.f, dot0, pa.w + pj.w);
            float r21  = fmaf(-2.f, dot1, pb.w + pj.w);
            float r20e = fmaxf(r20, 1e-6f);      // diagonal/negative -> finite
            float r21e = fmaxf(r21, 1e-6f);
            if (r20e < 56.25f) m0 |= (1u << b);  // predicated OR, no branch
            if (r21e < 56.25f) m1 |= (1u << b);
            acc0 = fmaf(qj, rsq(r20e), acc0);    // q_j / r, every pair
            acc1 = fmaf(qj, rsq(r21e), acc1);
        }
        // Fixups: lanes walk their own (rare) bits concurrently.
        while (m0) {
            int b = __ffs(m0) - 1;
            m0 &= m0 - 1;
            int j = w * 32 + b;
            float4 pj = sp[j];
            float dot = fmaf(pa.z, pj.z, fmaf(pa.y, pj.y, pa.x * pj.x));
            float r2  = fmaf(-2.f, dot, pa.w + pj.w);
            float r2e = fmaxf(r2, 1e-6f);
            acc0 = fmaf(-sqv[j], rsq(r2e), acc0);   // remove bogus (bitwise)
            if (r2 > 0.f) {
                float term;
                if (r2 <= 6.25f) {
                    term = rsq(r2 + 1.f);            // fs == 1
                } else {
                    float ir  = rsq(r2);
                    float r   = r2 * ir;
                    float arg = (r - 2.5f) * 0.2f;
                    float su  = __expf(-__fdividef(1.f, 1.f - arg));
                    float sd  = __expf(-__fdividef(1.f, arg));
                    float fs  = __fdividef(su, su + sd);
                    term = fmaf(fs, rsq(r2 + 1.f), (1.f - fs) * ir);
                }
                acc0 = fmaf(sqv[j], term, acc0);
            }
        }
        while (m1) {
            int b = __ffs(m1) - 1;
            m1 &= m1 - 1;
            int j = w * 32 + b;
            float4 pj = sp[j];
            float dot = fmaf(pb.z, pj.z, fmaf(pb.y, pj.y, pb.x * pj.x));
            float r2  = fmaf(-2.f, dot, pb.w + pj.w);
            float r2e = fmaxf(r2, 1e-6f);
            acc1 = fmaf(-sqv[j], rsq(r2e), acc1);   // remove bogus (bitwise)
            if (r2 > 0.f) {
                float term;
                if (r2 <= 6.25f) {
                    term = rsq(r2 + 1.f);            // fs == 1
                } else {
                    float ir  = rsq(r2);
                    float r   = r2 * ir;
                    float arg = (r - 2.5f) * 0.2f;
                    float su  = __expf(-__fdividef(1.f, 1.f - arg));
                    float sd  = __expf(-__fdividef(1.f, arg));
                    float fs  = __fdividef(su, su + sd);
                    term = fmaf(fs, rsq(r2 + 1.f), (1.f - fs) * ir);
                }
                acc1 = fmaf(sqv[j], term, acc1);
            }
        }
    }
    double a = (double)(acc0 * qa) + (double)(acc1 * qb);
    if (bx != by) a *= 2.0;

    int lane = tid & 31, wid = tid >> 5;
#pragma unroll
    for (int o = 16; o; o >>= 1)
        a += __shfl_xor_sync(0xffffffffu, a, o);
    if (lane == 0) wsum[wid] = a;
    __syncthreads();
    if (tid == 0) {
        double t = 0.0;
#pragma unroll
        for (int k = 0; k < TB / 32; k++) t += wsum[k];
        g_part[blockIdx.x] = t;
        __threadfence();
        int old = atomicAdd(&g_count, 1);
        s_last = (old == NBLK - 1);
    }
    __syncthreads();

    if (s_last) {                          // last block: final reduction
        __threadfence();
        double s = 0.0;
        for (int k = tid; k < NBLK; k += TB)   // fixed order -> deterministic
            s += g_part[k];
#pragma unroll
        for (int o = 16; o; o >>= 1)
            s += __shfl_xor_sync(0xffffffffu, s, o);
        if (lane == 0) wsum[wid] = s;
        __syncthreads();
        if (tid == 0) {
            double tot = 0.0;
#pragma unroll
            for (int k = 0; k < TB / 32; k++) tot += wsum[k];
            out[0] = (float)(KE_KCAL * 0.5 * tot);
            g_count = 0;                   // reset for next graph replay
        }
    }
}

// ---------------------------------------------------------------------------
extern "C" void kernel_launch(void* const* d_in, const int* in_sizes, int n_in,
                              void* d_out, int out_size)
{
    const float* f    = (const float*)d_in[0];
    const int*   z    = (const int*)  d_in[1];
    const float* xyz  = (const float*)d_in[2];
    const float* tc   = (const float*)d_in[3];
    const float* w    = (const float*)d_in[4];
    const float* ztab = (const float*)d_in[5];
    float* out = (float*)d_out;

    k_charge<<<384, 256>>>((const float4*)f, z, (const float4*)w, ztab);
    k_q<<<N_ATOMS / 256, 256>>>(xyz, tc, out + 1);
    k_dummy<<<1, 32>>>();                  // profiling alignment (capture = launch #4)
    k_pairs<<<NBLK, TB>>>(out);
}